// round 16
// baseline (speedup 1.0000x reference)
#include <cuda_runtime.h>
#include <cuda_fp16.h>
#include <math.h>

typedef unsigned int u32;
typedef unsigned long long u64;

#define NSTEPS 511
#define Tt     512
#define NTHR   256
#define MROWS  128

// ---- smem byte offsets ----
#define SM_W1 0            // 16 tiles * 512B
#define SM_W2 8192         // 32 tiles
#define SM_W3 24576        // 48 tiles
#define SM_KST 49152       // packed k-state: u64[5 stages][8][NTHR]
#define SMEM_BYTES (SM_KST + 5*8*NTHR*8)   // 131,072 B

__constant__ float cA6[6][5] = {
    {0.f,0.f,0.f,0.f,0.f},
    {0.161f,0.f,0.f,0.f,0.f},
    {-0.008480655492356989f,0.335480655492357f,0.f,0.f,0.f},
    {2.8971530571054935f,-6.359448489975075f,4.3622954328695815f,0.f,0.f},
    {5.325864828439257f,-11.748883564062828f,7.4955393428898365f,-0.09249506636175525f,0.f},
    {5.86145544294642f,-12.92096931784711f,8.159367898576159f,-0.071584973281401f,-0.028269050394068383f}};
__constant__ float cBt[6] = {
    0.09646076681806523f,0.01f,0.4798896504144996f,
    1.379008574103742f,-3.290069515436081f,2.324710524099774f};

// ---- packed f32x2 helpers ----
__device__ __forceinline__ u64 pack2(float lo, float hi){
    u64 r; asm("mov.b64 %0, {%1, %2};" : "=l"(r) : "f"(lo), "f"(hi)); return r;
}
__device__ __forceinline__ void unpack2(u64 v, float& lo, float& hi){
    asm("mov.b64 {%0, %1}, %2;" : "=f"(lo), "=f"(hi) : "l"(v));
}
__device__ __forceinline__ u64 fma2(u64 a, u64 b, u64 c){
    u64 d; asm("fma.rn.f32x2 %0, %1, %2, %3;" : "=l"(d) : "l"(a), "l"(b), "l"(c)); return d;
}

// fast tanh: 1 - 2/(2^(x*2/ln2)+1). 2 MUFU + 3 fma-pipe ops, ~1e-6 err.
__device__ __forceinline__ float ftanh(float x){
    float r;
    asm("{\n\t.reg .f32 e;\n\t"
        "mul.f32 e, %1, 0f4038AA3B;\n\t"
        "ex2.approx.f32 e, e;\n\t"
        "add.f32 e, e, 0f3F800000;\n\t"
        "rcp.approx.f32 e, e;\n\t"
        "fma.rn.f32 %0, e, 0fC0000000, 0f3F800000;\n\t"
        "}" : "=f"(r) : "f"(x));
    return r;
}

// packed hi/lo split: hi = f16x2(x,y), lo = f16x2 of residuals
__device__ __forceinline__ void split2(float x, float y, u32& hi, u32& lo){
    asm("cvt.rn.f16x2.f32 %0, %1, %2;" : "=r"(hi) : "f"(y), "f"(x));
    float hx, hy;
    asm("{\n\t.reg .f16 a,b;\n\tmov.b32 {a,b}, %2;\n\t"
        "cvt.f32.f16 %0, a;\n\tcvt.f32.f16 %1, b;\n\t}"
        : "=f"(hx), "=f"(hy) : "r"(hi));
    asm("cvt.rn.f16x2.f32 %0, %1, %2;" : "=r"(lo) : "f"(y-hy), "f"(x-hx));
}

// physical A-col p (0..31) -> logical h index
__device__ __forceinline__ int hphys(int p){
    return 8*((p&7)>>1) + 2*(p>>3) + (p&1);
}
// physical L3 out col p3 (0..95) -> logical w3 row (3h+c)
__device__ __forceinline__ int w3row(int p3){
    int j = p3>>3, r = p3&7, tg = r>>1, e = r&1;
    int q = 2*j + e, d = q/3, c = q%3;
    return 3*(8*tg + d) + c;
}

__device__ __forceinline__ void mma16816(float* c, const u32* a, u32 b0, u32 b1){
    asm("mma.sync.aligned.m16n8k16.row.col.f32.f16.f16.f32 "
        "{%0,%1,%2,%3}, {%4,%5,%6,%7}, {%8,%9}, {%0,%1,%2,%3};"
        : "+f"(c[0]), "+f"(c[1]), "+f"(c[2]), "+f"(c[3])
        : "r"(a[0]), "r"(a[1]), "r"(a[2]), "r"(a[3]), "r"(b0), "r"(b1));
}

// L1 form: A-fragments prebuilt (from stage combine)
template<int NJ, int NT>
__device__ __forceinline__ void runLayer(const u32* __restrict__ tiles,
                                         const float2* bias,
                                         const u32 (*ah)[4], const u32 (*al)[4],
                                         float (*C)[4], int lane)
{
    #pragma unroll
    for (int j=0;j<NJ;++j){
        C[j][0]=bias[j].x; C[j][1]=bias[j].y; C[j][2]=bias[j].x; C[j][3]=bias[j].y;
    }
    #pragma unroll
    for (int t=0;t<NT;++t){
        uint4 w[NJ];
        #pragma unroll
        for (int j=0;j<NJ;++j)
            w[j] = *(const uint4*)(tiles + (j*NT+t)*128 + lane*4);
        #pragma unroll
        for (int j=0;j<NJ;++j) mma16816(C[j], ah[t], w[j].x, w[j].y);  // Ah*Bh
        #pragma unroll
        for (int j=0;j<NJ;++j) mma16816(C[j], al[t], w[j].x, w[j].y);  // Al*Bh
        #pragma unroll
        for (int j=0;j<NJ;++j) mma16816(C[j], ah[t], w[j].z, w[j].w);  // Ah*Bl
    }
}

// Fused form: per k-tile, tanh+split the previous layer's C pair, then
// immediately issue that tile's MMAs — overlaps MUFU bursts with tensor.
// Accumulation order per C[j] identical to runLayer.
template<int NJ, int NT>
__device__ __forceinline__ void fusedLayer(const u32* __restrict__ tiles,
                                           const float2* bias,
                                           const float (*Cp)[4],
                                           float (*C)[4], int lane)
{
    #pragma unroll
    for (int j=0;j<NJ;++j){
        C[j][0]=bias[j].x; C[j][1]=bias[j].y; C[j][2]=bias[j].x; C[j][3]=bias[j].y;
    }
    #pragma unroll
    for (int t=0;t<NT;++t){
        u32 ah[4], al[4];
        split2(ftanh(Cp[2*t][0]),   ftanh(Cp[2*t][1]),   ah[0], al[0]);
        split2(ftanh(Cp[2*t][2]),   ftanh(Cp[2*t][3]),   ah[1], al[1]);
        split2(ftanh(Cp[2*t+1][0]), ftanh(Cp[2*t+1][1]), ah[2], al[2]);
        split2(ftanh(Cp[2*t+1][2]), ftanh(Cp[2*t+1][3]), ah[3], al[3]);
        uint4 w[NJ];
        #pragma unroll
        for (int j=0;j<NJ;++j)
            w[j] = *(const uint4*)(tiles + (j*NT+t)*128 + lane*4);
        #pragma unroll
        for (int j=0;j<NJ;++j) mma16816(C[j], ah, w[j].x, w[j].y);  // Ah*Bh
        #pragma unroll
        for (int j=0;j<NJ;++j) mma16816(C[j], al, w[j].x, w[j].y);  // Al*Bh
        #pragma unroll
        for (int j=0;j<NJ;++j) mma16816(C[j], ah, w[j].z, w[j].w);  // Ah*Bl
    }
}

__global__ void __launch_bounds__(NTHR, 1)
ncde_mma(const float* __restrict__ times, const float* __restrict__ grad,
         const float* __restrict__ w1, const float* __restrict__ pb1,
         const float* __restrict__ w2, const float* __restrict__ pb2,
         const float* __restrict__ w3, const float* __restrict__ pb3,
         const float* __restrict__ w_enc, const float* __restrict__ b_enc,
         const float* __restrict__ w_ro, const float* __restrict__ b_ro,
         float* __restrict__ out, int Bn)
{
    extern __shared__ float sm[];
    char* smc = (char*)sm;
    u32* tw1 = (u32*)(smc + SM_W1);
    u32* tw2 = (u32*)(smc + SM_W2);
    u32* tw3 = (u32*)(smc + SM_W3);
    u64* kbuf = (u64*)(smc + SM_KST);   // [(p*8+j)*NTHR + tid]

    const int tid = threadIdx.x, warp = tid>>5, lane = tid&31;
    const int g = lane>>2, tg = lane&3;

    // ---- build weight fragment tiles (hi/lo f16) ----
    for (int s = tid; s < 16*32; s += NTHR){
        int tile = s>>5, l = s&31;
        int j = tile>>1, t = tile&1;
        int gg = l>>2, tt = l&3;
        int n = 8*j+gg, k0 = 16*t+2*tt;
        float f0 = w1[n*32 + hphys(k0)],   f1 = w1[n*32 + hphys(k0+1)];
        float f8 = w1[n*32 + hphys(k0+8)], f9 = w1[n*32 + hphys(k0+9)];
        u32 h01,l01,h89,l89;
        split2(f0,f1,h01,l01); split2(f8,f9,h89,l89);
        u32* d = tw1 + tile*128 + l*4;
        d[0]=h01; d[1]=h89; d[2]=l01; d[3]=l89;
    }
    for (int s = tid; s < 32*32; s += NTHR){
        int tile = s>>5, l = s&31;
        int j = tile>>2, t = tile&3;
        int gg = l>>2, tt = l&3;
        int n = 8*j+gg, k0 = 16*t+2*tt;
        float f0 = w2[n*64+k0],   f1 = w2[n*64+k0+1];
        float f8 = w2[n*64+k0+8], f9 = w2[n*64+k0+9];
        u32 h01,l01,h89,l89;
        split2(f0,f1,h01,l01); split2(f8,f9,h89,l89);
        u32* d = tw2 + tile*128 + l*4;
        d[0]=h01; d[1]=h89; d[2]=l01; d[3]=l89;
    }
    for (int s = tid; s < 48*32; s += NTHR){
        int tile = s>>5, l = s&31;
        int j = tile>>2, t = tile&3;
        int gg = l>>2, tt = l&3;
        int n = 8*j+gg, k0 = 16*t+2*tt;
        int rr = w3row(n);
        float f0 = w3[rr*64+k0],   f1 = w3[rr*64+k0+1];
        float f8 = w3[rr*64+k0+8], f9 = w3[rr*64+k0+9];
        u32 h01,l01,h89,l89;
        split2(f0,f1,h01,l01); split2(f8,f9,h89,l89);
        u32* d = tw3 + tile*128 + l*4;
        d[0]=h01; d[1]=h89; d[2]=l01; d[3]=l89;
    }
    __syncthreads();

    // ---- biases in registers (per-thread fragment slices) ----
    float2 b1f[8], b2f[8], b3f[12];
    #pragma unroll
    for (int j=0;j<8;++j){
        b1f[j] = make_float2(pb1[8*j+2*tg], pb1[8*j+2*tg+1]);
        b2f[j] = make_float2(pb2[8*j+2*tg], pb2[8*j+2*tg+1]);
    }
    #pragma unroll
    for (int j=0;j<12;++j)
        b3f[j] = make_float2(pb3[w3row(8*j+2*tg)], pb3[w3row(8*j+2*tg+1)]);

    // ---- per-thread state: rows g and g+8 of warp's 16-row block ----
    const int base = blockIdx.x*MROWS + warp*16;
    const int rowg = base + g, rowh = rowg + 8;
    const int rgc = (rowg < Bn) ? rowg : (Bn-1);
    const int rhc = (rowh < Bn) ? rowh : (Bn-1);
    const float dt = times[1] - times[0];
    const float* gA = grad + (size_t)rgc * (Tt*3);
    const float* gB = grad + (size_t)rhc * (Tt*3);

    // packed z state
    u64 zg2[4], zh2[4];
    #pragma unroll
    for (int j=0;j<4;++j){
        float v0 = w_enc[8*tg+2*j]   + b_enc[8*tg+2*j];
        float v1 = w_enc[8*tg+2*j+1] + b_enc[8*tg+2*j+1];
        zg2[j] = pack2(v0, v1);
        zh2[j] = pack2(v0, v1);
    }

    // dq double-buffer
    float pA0 = gA[0], pA1 = gA[1], pA2 = gA[2];
    float pB0 = gB[0], pB1 = gB[1], pB2 = gB[2];

    #pragma unroll 1
    for (int n=0; n<NSTEPS; ++n){
        const float dqg[3] = {pA0*dt, pA1*dt, pA2*dt};
        const float dqh[3] = {pB0*dt, pB1*dt, pB2*dt};
        if (n + 1 < NSTEPS){
            const float* a = gA + (n+1)*3;
            const float* b = gB + (n+1)*3;
            pA0 = a[0]; pA1 = a[1]; pA2 = a[2];
            pB0 = b[0]; pB1 = b[1]; pB2 = b[2];
        }

        #pragma unroll 1
        for (int sg=0; sg<6; ++sg){
            // ---- stage combine (packed): Y = z + sum_p A[sg][p] k_p ----
            u64 Yg2[4], Yh2[4];
            #pragma unroll
            for (int j=0;j<4;++j){ Yg2[j]=zg2[j]; Yh2[j]=zh2[j]; }
            for (int p=0;p<sg;++p){
                const float c = cA6[sg][p];
                const u64 cc = pack2(c, c);
                #pragma unroll
                for (int j=0;j<4;++j){
                    Yg2[j] = fma2(cc, kbuf[(p*8+j)*NTHR+tid],   Yg2[j]);
                    Yh2[j] = fma2(cc, kbuf[(p*8+4+j)*NTHR+tid], Yh2[j]);
                }
            }
            u32 yah[2][4], yal[2][4];
            #pragma unroll
            for (int t=0;t<2;++t){
                float x, y;
                unpack2(Yg2[2*t],   x, y); split2(x, y, yah[t][0], yal[t][0]);
                unpack2(Yh2[2*t],   x, y); split2(x, y, yah[t][1], yal[t][1]);
                unpack2(Yg2[2*t+1], x, y); split2(x, y, yah[t][2], yal[t][2]);
                unpack2(Yh2[2*t+1], x, y); split2(x, y, yah[t][3], yal[t][3]);
            }

            // ---- L1 (A-frags prebuilt) ----
            float C1[8][4];
            runLayer<8,2>(tw1, b1f, yah, yal, C1, lane);

            // ---- L2 fused (tanh/split per tile, interleaved with MMA) ----
            float C2[8][4];
            fusedLayer<8,4>(tw2, b2f, C1, C2, lane);

            // ---- L3 fused ----
            float C3[12][4];
            fusedLayer<12,4>(tw3, b3f, C2, C3, lane);

            // ---- dq contraction -> k ----
            float nkg[8], nkh[8];
            #pragma unroll
            for (int d=0;d<8;++d){ nkg[d]=0.f; nkh[d]=0.f; }
            #pragma unroll
            for (int j=0;j<12;++j){
                #pragma unroll
                for (int e=0;e<2;++e){
                    const int q = 2*j+e, d = q/3, c = q%3;
                    nkg[d] = fmaf(C3[j][e],   dqg[c], nkg[d]);
                    nkh[d] = fmaf(C3[j][2+e], dqh[c], nkh[d]);
                }
            }

            if (sg < 5){
                #pragma unroll
                for (int j=0;j<4;++j){
                    kbuf[(sg*8+j)*NTHR+tid]   = pack2(nkg[2*j], nkg[2*j+1]);
                    kbuf[(sg*8+4+j)*NTHR+tid] = pack2(nkh[2*j], nkh[2*j+1]);
                }
            } else {
                // ---- z += sum_p B[p] k_p (k5 straight from registers) ----
                #pragma unroll
                for (int p=0;p<5;++p){
                    const u64 cc = pack2(cBt[p], cBt[p]);
                    #pragma unroll
                    for (int j=0;j<4;++j){
                        zg2[j] = fma2(cc, kbuf[(p*8+j)*NTHR+tid],   zg2[j]);
                        zh2[j] = fma2(cc, kbuf[(p*8+4+j)*NTHR+tid], zh2[j]);
                    }
                }
                const u64 c5 = pack2(cBt[5], cBt[5]);
                #pragma unroll
                for (int j=0;j<4;++j){
                    zg2[j] = fma2(c5, pack2(nkg[2*j], nkg[2*j+1]), zg2[j]);
                    zh2[j] = fma2(c5, pack2(nkh[2*j], nkh[2*j+1]), zh2[j]);
                }
            }
        }
    }

    // ---- readout ----
    float pg = 0.f, ph = 0.f;
    #pragma unroll
    for (int j=0;j<4;++j){
        float a, b;
        unpack2(zg2[j], a, b);
        pg = fmaf(a, w_ro[8*tg+2*j], pg);
        pg = fmaf(b, w_ro[8*tg+2*j+1], pg);
        unpack2(zh2[j], a, b);
        ph = fmaf(a, w_ro[8*tg+2*j], ph);
        ph = fmaf(b, w_ro[8*tg+2*j+1], ph);
    }
    pg += __shfl_xor_sync(0xffffffffu, pg, 1);
    pg += __shfl_xor_sync(0xffffffffu, pg, 2);
    ph += __shfl_xor_sync(0xffffffffu, ph, 1);
    ph += __shfl_xor_sync(0xffffffffu, ph, 2);
    if (tg == 0){
        const float br = b_ro[0];
        if (rowg < Bn) out[rowg] = 1.0f/(1.0f + expf(-(pg + br)));
        if (rowh < Bn) out[rowh] = 1.0f/(1.0f + expf(-(ph + br)));
    }
}

extern "C" void kernel_launch(void* const* d_in, const int* in_sizes, int n_in,
                              void* d_out, int out_size)
{
    const float* times=(const float*)d_in[0];
    const float* grad =(const float*)d_in[1];
    const float* w1=(const float*)d_in[2];  const float* b1=(const float*)d_in[3];
    const float* w2=(const float*)d_in[4];  const float* b2=(const float*)d_in[5];
    const float* w3=(const float*)d_in[6];  const float* b3=(const float*)d_in[7];
    const float* we=(const float*)d_in[8];  const float* be=(const float*)d_in[9];
    const float* wr=(const float*)d_in[10]; const float* br=(const float*)d_in[11];
    float* out=(float*)d_out;

    const int Bn = in_sizes[1] / (Tt*3);
    const int nblocks = (Bn + MROWS - 1) / MROWS;

    cudaFuncSetAttribute(ncde_mma, cudaFuncAttributeMaxDynamicSharedMemorySize,
                         (int)SMEM_BYTES);
    ncde_mma<<<nblocks, NTHR, SMEM_BYTES>>>(
        times, grad, w1, b1, w2, b2, w3, b3, we, be, wr, br, out, Bn);
}